// round 6
// baseline (speedup 1.0000x reference)
#include <cuda_runtime.h>
#include <cuda_fp16.h>
#include <cstdint>
#include <math.h>

#define TOKS 512
#define HDIM 1024
#define FDIM 4096
#define NEXP 8
#define SLOT 512
#define SSTH 40                       // halves per A smem row
#define SSTF 36                       // floats per B smem row
#define A64H  (64 * SSTH)             // 2560 halves / stage
#define A128H (128 * SSTH)            // 5120 halves / stage
#define BSTF  (64 * SSTF)             // 2304 floats / stage (9216 B)
#define KSPLIT 4

// ---------------- scratch (static device globals) ---------------------------
__device__ __half d_xh[TOKS * HDIM];                    // fp16 x
__device__ __half d_h[NEXP * SLOT * FDIM];              // fp16 intermediate h
__device__ float  d_po[KSPLIT * NEXP * SLOT * HDIM];    // split-K partials
__device__ int    d_count[NEXP];
__device__ int    d_tok[NEXP * SLOT];
__device__ float  d_mult[NEXP * SLOT];
__device__ int    d_pidx[TOKS * 2];

// ---------------- helpers ----------------------------------------------------
__device__ __forceinline__ unsigned pk2(float a, float b) {
    __half2 h = __floats2half2_rn(a, b);
    return *(unsigned*)&h;
}
__device__ __forceinline__ void mma16(float* c, const unsigned* a, const unsigned* b) {
    asm volatile(
        "mma.sync.aligned.m16n8k16.row.col.f32.f16.f16.f32 "
        "{%0,%1,%2,%3}, {%4,%5,%6,%7}, {%8,%9}, {%0,%1,%2,%3};"
        : "+f"(c[0]), "+f"(c[1]), "+f"(c[2]), "+f"(c[3])
        : "r"(a[0]), "r"(a[1]), "r"(a[2]), "r"(a[3]), "r"(b[0]), "r"(b[1]));
}
__device__ __forceinline__ void ldsm4(unsigned* r, unsigned addr) {
    asm volatile("ldmatrix.sync.aligned.m8n8.x4.shared.b16 {%0,%1,%2,%3}, [%4];"
        : "=r"(r[0]), "=r"(r[1]), "=r"(r[2]), "=r"(r[3]) : "r"(addr));
}
__device__ __forceinline__ void cpa(unsigned dst, const void* src) {
    asm volatile("cp.async.cg.shared.global [%0], [%1], 16;" :: "r"(dst), "l"(src));
}
#define CP_COMMIT asm volatile("cp.async.commit_group;")
#define CP_WAIT1  asm volatile("cp.async.wait_group 1;")

// build B fragment pair from fp32 smem row (n-major, SSTF floats/row)
__device__ __forceinline__ void bfrag(const float* rowp, unsigned* br) {
    float2 lo = *(const float2*)rowp;
    float2 hi = *(const float2*)(rowp + 8);
    br[0] = pk2(lo.x, lo.y);
    br[1] = pk2(hi.x, hi.y);
}

// ---------------- init / convx ----------------------------------------------
__global__ void init_kernel() {
    if (threadIdx.x < NEXP) d_count[threadIdx.x] = 0;
}
__global__ void convx_kernel(const float* __restrict__ x) {
    int i = (blockIdx.x * 256 + threadIdx.x) * 4;
    float4 v = *(const float4*)(x + i);
    uint2 o; o.x = pk2(v.x, v.y); o.y = pk2(v.z, v.w);
    *(uint2*)&d_xh[i] = o;
}

// ---------------- routing ---------------------------------------------------
__global__ void routing_kernel(const float* __restrict__ x,
                               const float* __restrict__ gw) {
    int t = blockIdx.x;
    int tid = threadIdx.x;
    int w = tid >> 5, lane = tid & 31;
    __shared__ float lg[NEXP];

    const float* xr = x + (size_t)t * HDIM;
    const float* gr = gw + (size_t)w * HDIM;
    float s = 0.f;
    for (int i = lane * 4; i < HDIM; i += 128) {
        float4 a = *(const float4*)(xr + i);
        float4 b = *(const float4*)(gr + i);
        s += a.x * b.x + a.y * b.y + a.z * b.z + a.w * b.w;
    }
    #pragma unroll
    for (int o = 16; o; o >>= 1) s += __shfl_xor_sync(0xFFFFFFFFu, s, o);
    if (lane == 0) lg[w] = s;
    __syncthreads();

    if (tid == 0) {
        float l[NEXP];
        #pragma unroll
        for (int e = 0; e < NEXP; e++) l[e] = lg[e];

        int s1 = 0;
        for (int e = 1; e < NEXP; e++) if (l[e] > l[s1]) s1 = e;
        float m1 = l[s1];
        int s2 = (s1 == 0) ? 1 : 0;
        for (int e = 0; e < NEXP; e++) { if (e == s1) continue; if (l[e] > l[s2]) s2 = e; }
        float m2 = l[s2];

        float mult1, mult2;
        {
            float keep[NEXP]; float mx = -1e30f;
            for (int e = 0; e < NEXP; e++) {
                float f = fmaxf(fabsf(l[e]), m1);
                keep[e] = ((m1 - l[e]) / f > 0.02f) ? -1e30f : l[e];
                mx = fmaxf(mx, keep[e]);
            }
            float sum = 0.f, num = 0.f;
            for (int e = 0; e < NEXP; e++) {
                float p = (keep[e] <= -1e30f) ? 0.f : expf(keep[e] - mx);
                sum += p; if (e == s1) num = p;
            }
            mult1 = num / sum;
        }
        {
            float keep[NEXP]; float mx = -1e30f;
            for (int e = 0; e < NEXP; e++) {
                float f = fmaxf(fabsf(l[e]), m2);
                bool msk = ((m2 - l[e]) / f > 0.02f) || (e == s1);
                keep[e] = msk ? -1e30f : l[e];
                mx = fmaxf(mx, keep[e]);
            }
            float sum = 0.f, num = 0.f;
            for (int e = 0; e < NEXP; e++) {
                float p = (keep[e] <= -1e30f) ? 0.f : expf(keep[e] - mx);
                sum += p; if (e == s2) num = p;
            }
            mult2 = num / sum;
        }

        int p = atomicAdd(&d_count[s1], 1);
        d_tok[s1 * SLOT + p] = t; d_mult[s1 * SLOT + p] = mult1;
        d_pidx[t * 2 + 0] = s1 * SLOT + p;
        p = atomicAdd(&d_count[s2], 1);
        d_tok[s2 * SLOT + p] = t; d_mult[s2 * SLOT + p] = mult2;
        d_pidx[t * 2 + 1] = s2 * SLOT + p;
    }
}

// ---------------- GEMM1: 64x64, fused w1/w3, all-cp.async, fp16 mma ---------
__global__ __launch_bounds__(256, 3) void gemm1_kernel(const float* __restrict__ w1,
                                                       const float* __restrict__ w3) {
    extern __shared__ char smraw[];
    __half* Ab  = (__half*)smraw;                         // 3 * A64H halves
    float*  B1b = (float*)(smraw + 3 * A64H * 2);         // 3 * BSTF floats
    float*  B3b = (float*)(smraw + 3 * A64H * 2 + 3 * BSTF * 4);

    int e = blockIdx.y >> 3, mtile = blockIdx.y & 7;
    int cnt = d_count[e];
    int m0 = mtile * 64;
    if (m0 >= cnt) return;
    int n0 = blockIdx.x * 64;

    int tid = threadIdx.x;
    // A cp.async: 1 chunk/thread (64 rows x 4 chunks of 8 halves)
    int arow = tid >> 2, ac = tid & 3;
    int rr = m0 + arow; if (rr >= cnt) rr = cnt - 1;
    const __half* aptr = d_xh + (size_t)d_tok[e * SLOT + rr] * HDIM + ac * 8;
    unsigned aoffs = (unsigned)(arow * SSTH + ac * 8) * 2;

    // B cp.async: 2 chunks/thread each matrix (64 rows x 8 chunks of 4 floats)
    const float* b1p[2]; const float* b3p[2]; unsigned boffs[2];
    #pragma unroll
    for (int j = 0; j < 2; j++) {
        int gidx = tid + 256 * j;
        int row = gidx >> 3, c = gidx & 7;
        b1p[j] = w1 + ((size_t)e * FDIM + n0 + row) * HDIM + c * 4;
        b3p[j] = w3 + ((size_t)e * FDIM + n0 + row) * HDIM + c * 4;
        boffs[j] = (unsigned)(row * SSTF + c * 4) * 4;
    }

    unsigned uA  = (unsigned)__cvta_generic_to_shared(Ab);
    unsigned uB1 = (unsigned)__cvta_generic_to_shared(B1b);
    unsigned uB3 = (unsigned)__cvta_generic_to_shared(B3b);

    const int NKT = HDIM / 32;  // 32

    #pragma unroll
    for (int s = 0; s < 2; s++) {
        cpa(uA + (unsigned)s * (A64H * 2) + aoffs, aptr + s * 32);
        #pragma unroll
        for (int j = 0; j < 2; j++) {
            cpa(uB1 + (unsigned)s * (BSTF * 4) + boffs[j], b1p[j] + s * 32);
            cpa(uB3 + (unsigned)s * (BSTF * 4) + boffs[j], b3p[j] + s * 32);
        }
        CP_COMMIT;
    }

    int warp = tid >> 5, lane = tid & 31;
    int wm = warp >> 2, wn = warp & 3;     // 2 x 4 warps, warp tile 32x16
    int g = lane >> 2, tg = lane & 3;
    int bq = lane & 3, bn = lane >> 2;

    unsigned aoffm[2];
    #pragma unroll
    for (int mi = 0; mi < 2; mi++)
        aoffm[mi] = (unsigned)((wm * 32 + mi * 16 + (lane & 7) + ((lane >> 3) & 1) * 8) * SSTH
                               + (lane >> 4) * 8) * 2;

    float acc1[2][2][4] = {}, acc3[2][2][4] = {};

    for (int kt = 0; kt < NKT; kt++) {
        CP_WAIT1;
        __syncthreads();
        int kn = kt + 2;
        if (kn < NKT) {
            int st = kn % 3;
            cpa(uA + (unsigned)st * (A64H * 2) + aoffs, aptr + kn * 32);
            #pragma unroll
            for (int j = 0; j < 2; j++) {
                cpa(uB1 + (unsigned)st * (BSTF * 4) + boffs[j], b1p[j] + kn * 32);
                cpa(uB3 + (unsigned)st * (BSTF * 4) + boffs[j], b3p[j] + kn * 32);
            }
        }
        CP_COMMIT;

        unsigned sAc = uA + (unsigned)(kt % 3) * (A64H * 2);
        const float* B1c = B1b + (kt % 3) * BSTF;
        const float* B3c = B3b + (kt % 3) * BSTF;

        #pragma unroll
        for (int ks = 0; ks < 2; ks++) {
            unsigned af[2][4];
            ldsm4(af[0], sAc + aoffm[0] + ks * 32);
            ldsm4(af[1], sAc + aoffm[1] + ks * 32);
            int k0 = ks * 16 + 2 * bq;
            #pragma unroll
            for (int ni = 0; ni < 2; ni++) {
                int rowb = (wn * 16 + ni * 8 + bn) * SSTF + k0;
                unsigned br1[2], br3[2];
                bfrag(B1c + rowb, br1);
                bfrag(B3c + rowb, br3);
                #pragma unroll
                for (int mi = 0; mi < 2; mi++) {
                    mma16(acc1[mi][ni], af[mi], br1);
                    mma16(acc3[mi][ni], af[mi], br3);
                }
            }
        }
    }

    // epilogue: silu(s1) * s3 -> d_h (fp16)
    #pragma unroll
    for (int mi = 0; mi < 2; mi++)
    #pragma unroll
    for (int ni = 0; ni < 2; ni++)
    #pragma unroll
    for (int h = 0; h < 2; h++) {
        int lr = wm * 32 + mi * 16 + g + h * 8;
        if (m0 + lr < cnt) {
            int col = n0 + wn * 16 + ni * 8 + tg * 2;
            float v1a = acc1[mi][ni][h * 2], v1b = acc1[mi][ni][h * 2 + 1];
            float v3a = acc3[mi][ni][h * 2], v3b = acc3[mi][ni][h * 2 + 1];
            float h0 = v1a * v3a / (1.f + __expf(-v1a));
            float h1 = v1b * v3b / (1.f + __expf(-v1b));
            unsigned u = pk2(h0, h1);
            *(unsigned*)&d_h[((size_t)(e * SLOT + m0 + lr)) * FDIM + col] = u;
        }
    }
}

// ---------------- GEMM2: 128x64, split-K x4, all-cp.async, fp16 mma ---------
__global__ __launch_bounds__(256, 3) void gemm2_kernel(const float* __restrict__ w2) {
    extern __shared__ char smraw[];
    __half* Ab = (__half*)smraw;                          // 3 * A128H halves
    float*  Bb = (float*)(smraw + 3 * A128H * 2);         // 3 * BSTF floats

    int e = blockIdx.y >> 2, mtile = blockIdx.y & 3;
    int cnt = d_count[e];
    int m0 = mtile * 128;
    if (m0 >= cnt) return;
    int n0 = blockIdx.x * 64;
    int kz = blockIdx.z;
    int kbase = kz * (FDIM / KSPLIT);

    int tid = threadIdx.x;
    const __half* aptr[2]; unsigned aoffs[2];
    #pragma unroll
    for (int j = 0; j < 2; j++) {
        int gidx = tid + 256 * j;
        int row = gidx >> 2, c = gidx & 3;
        int rr = m0 + row; if (rr >= cnt) rr = cnt - 1;
        aptr[j]  = d_h + ((size_t)(e * SLOT) + rr) * FDIM + kbase + c * 8;
        aoffs[j] = (unsigned)(row * SSTH + c * 8) * 2;
    }
    const float* bp[2]; unsigned boffs[2];
    #pragma unroll
    for (int j = 0; j < 2; j++) {
        int gidx = tid + 256 * j;
        int row = gidx >> 3, c = gidx & 7;
        bp[j]    = w2 + ((size_t)e * HDIM + n0 + row) * FDIM + kbase + c * 4;
        boffs[j] = (unsigned)(row * SSTF + c * 4) * 4;
    }

    unsigned uA = (unsigned)__cvta_generic_to_shared(Ab);
    unsigned uB = (unsigned)__cvta_generic_to_shared(Bb);

    const int NKT = (FDIM / KSPLIT) / 32;  // 32

    #pragma unroll
    for (int s = 0; s < 2; s++) {
        #pragma unroll
        for (int j = 0; j < 2; j++) {
            cpa(uA + (unsigned)s * (A128H * 2) + aoffs[j], aptr[j] + s * 32);
            cpa(uB + (unsigned)s * (BSTF * 4)  + boffs[j], bp[j]   + s * 32);
        }
        CP_COMMIT;
    }

    int warp = tid >> 5, lane = tid & 31;
    int wm = warp >> 1, wn = warp & 1;     // 4 x 2 warps, warp tile 32x32
    int g = lane >> 2, tg = lane & 3;
    int bq = lane & 3, bn = lane >> 2;

    unsigned aoffm[2];
    #pragma unroll
    for (int mi = 0; mi < 2; mi++)
        aoffm[mi] = (unsigned)((wm * 32 + mi * 16 + (lane & 7) + ((lane >> 3) & 1) * 8) * SSTH
                               + (lane >> 4) * 8) * 2;

    float acc[2][4][4] = {};

    for (int kt = 0; kt < NKT; kt++) {
        CP_WAIT1;
        __syncthreads();
        int kn = kt + 2;
        if (kn < NKT) {
            int st = kn % 3;
            #pragma unroll
            for (int j = 0; j < 2; j++) {
                cpa(uA + (unsigned)st * (A128H * 2) + aoffs[j], aptr[j] + kn * 32);
                cpa(uB + (unsigned)st * (BSTF * 4)  + boffs[j], bp[j]   + kn * 32);
            }
        }
        CP_COMMIT;

        unsigned sAc = uA + (unsigned)(kt % 3) * (A128H * 2);
        const float* Bc = Bb + (kt % 3) * BSTF;

        #pragma unroll
        for (int ks = 0; ks < 2; ks++) {
            unsigned af[2][4];
            ldsm4(af[0], sAc + aoffm[0] + ks * 32);
            ldsm4(af[1], sAc + aoffm[1] + ks * 32);
            int k0 = ks * 16 + 2 * bq;
            #pragma unroll
            for (int ni = 0; ni < 4; ni++) {
                int rowb = (wn * 32 + ni * 8 + bn) * SSTF + k0;
                unsigned br[2];
                bfrag(Bc + rowb, br);
                #pragma unroll
                for (int mi = 0; mi < 2; mi++)
                    mma16(acc[mi][ni], af[mi], br);
            }
        }
    }

    float* po = d_po + (size_t)kz * (NEXP * SLOT * HDIM);
    #pragma unroll
    for (int mi = 0; mi < 2; mi++)
    #pragma unroll
    for (int ni = 0; ni < 4; ni++)
    #pragma unroll
    for (int h = 0; h < 2; h++) {
        int lr = wm * 32 + mi * 16 + g + h * 8;
        if (m0 + lr < cnt) {
            float mult = d_mult[e * SLOT + m0 + lr];
            int col = n0 + wn * 32 + ni * 8 + tg * 2;
            float2 o;
            o.x = acc[mi][ni][h * 2]     * mult;
            o.y = acc[mi][ni][h * 2 + 1] * mult;
            *(float2*)&po[((size_t)(e * SLOT + m0 + lr)) * HDIM + col] = o;
        }
    }
}

// ---------------- finalize ---------------------------------------------------
__global__ void finalize_kernel(float* __restrict__ out) {
    int t = blockIdx.x;
    int i = threadIdx.x;
    int p0 = d_pidx[t * 2], p1 = d_pidx[t * 2 + 1];
    float4 o = make_float4(0.f, 0.f, 0.f, 0.f);
    #pragma unroll
    for (int kz = 0; kz < KSPLIT; kz++) {
        const float* po = d_po + (size_t)kz * (NEXP * SLOT * HDIM);
        float4 a = ((const float4*)(po + (size_t)p0 * HDIM))[i];
        float4 b = ((const float4*)(po + (size_t)p1 * HDIM))[i];
        o.x += a.x + b.x; o.y += a.y + b.y;
        o.z += a.z + b.z; o.w += a.w + b.w;
    }
    ((float4*)(out + (size_t)t * HDIM))[i] = o;
}

// ---------------- launch ----------------------------------------------------
extern "C" void kernel_launch(void* const* d_in, const int* in_sizes, int n_in,
                              void* d_out, int out_size) {
    const float* x  = (const float*)d_in[0];
    const float* gw = (const float*)d_in[1];
    const float* w1 = (const float*)d_in[2];
    const float* w2 = (const float*)d_in[3];
    const float* w3 = (const float*)d_in[4];
    float* out = (float*)d_out;

    const int smem1 = 3 * A64H * 2 + 6 * BSTF * 4;    // 15360 + 55296 = 70656 B
    const int smem2 = 3 * A128H * 2 + 3 * BSTF * 4;   // 30720 + 27648 = 58368 B
    cudaFuncSetAttribute(gemm1_kernel, cudaFuncAttributeMaxDynamicSharedMemorySize, smem1);
    cudaFuncSetAttribute(gemm2_kernel, cudaFuncAttributeMaxDynamicSharedMemorySize, smem2);

    init_kernel<<<1, 32>>>();
    convx_kernel<<<TOKS * HDIM / 1024, 256>>>(x);
    routing_kernel<<<TOKS, 256>>>(x, gw);
    gemm1_kernel<<<dim3(FDIM / 64, NEXP * 8), 256, smem1>>>(w1, w3);
    gemm2_kernel<<<dim3(HDIM / 64, NEXP * 4, KSPLIT), 256, smem2>>>(w2);
    finalize_kernel<<<TOKS, 256>>>(out);
}